// round 3
// baseline (speedup 1.0000x reference)
#include <cuda_runtime.h>
#include <math.h>

#define N_NODES 100000
#define N_EDGES 1600000
#define IN_F 128
#define OUT_F 128         // NHEAD*OUT = 4*32
#define NHEAD 4
#define SLOPE 0.2f

// ---------------- scratch (device globals; no allocation) ----------------
__device__ float4 g_h_tail[N_NODES * 32];   // [N,128] as float4  (51.2MB)
__device__ float4 g_hl[N_NODES];            // [N,4]
__device__ float4 g_hr[N_NODES];            // [N,4]
__device__ float4 g_att[N_EDGES];           // [E,4]
__device__ float4 g_satt[N_EDGES];          // sorted att
__device__ int    g_stail[N_EDGES];         // sorted tail index
__device__ int    g_count[N_NODES];
__device__ int    g_off[N_NODES + 1];
__device__ int    g_cursor[N_NODES];
__device__ float  g_wl[NHEAD * IN_F];       // W @ a_l per head
__device__ float  g_wr[NHEAD * IN_F];       // W @ a_r per head
__device__ float  g_he[8 * NHEAD];          // per (etype, head) scalar

// ---------------- tiny prep: w_l, w_r, edge-type table ----------------
__global__ void prep_kernel(const float* __restrict__ W,
                            const float* __restrict__ We,
                            const float* __restrict__ al,
                            const float* __restrict__ ar,
                            const float* __restrict__ ae,
                            const float* __restrict__ emb) {
    int tid = threadIdx.x;
    // w_l[h][i] = sum_d W[i, h*32+d] * a_l[h,d]
    if (tid < 512) {
        int h = tid >> 7, i = tid & 127;
        float sl = 0.f, sr = 0.f;
        #pragma unroll 8
        for (int d = 0; d < 32; d++) {
            float w = W[i * 128 + h * 32 + d];
            sl = fmaf(w, al[h * 32 + d], sl);
            sr = fmaf(w, ar[h * 32 + d], sr);
        }
        g_wl[h * 128 + i] = sl;
        g_wr[h * 128 + i] = sr;
    }
    __shared__ float u[32 * 4];   // u[k][h] = sum_de We[k, h*32+de]*a_e[h,de]
    if (tid < 128) {
        int k = tid >> 2, h = tid & 3;
        float s = 0.f;
        for (int de = 0; de < 32; de++)
            s = fmaf(We[k * 128 + h * 32 + de], ae[h * 32 + de], s);
        u[k * 4 + h] = s;
    }
    __syncthreads();
    if (tid < 32) {
        int t = tid >> 2, h = tid & 3;
        float s = 0.f;
        for (int k = 0; k < 32; k++)
            s = fmaf(emb[t * 32 + k], u[k * 4 + h], s);
        g_he[t * 4 + h] = s;
    }
}

// ---------------- GEMM: g_h_tail = tail_feature @ W  (100k x 128 x 128) ----------------
// block: 256 threads, 64 rows x 128 cols, K split into 4 chunks of 32.
__global__ __launch_bounds__(256) void gemm128_kernel(const float* __restrict__ X,
                                                      const float* __restrict__ W,
                                                      int n) {
    __shared__ float ws[32 * 128];    // 16KB current K-chunk of W
    __shared__ float xs[64 * 36];     // 9.2KB X tile (stride 36 -> 16B aligned, bank-shift 4)
    int tid = threadIdx.x;
    int tx = tid & 15, ty = tid >> 4;
    int row0 = blockIdx.x * 64;
    float c[4][8];
    #pragma unroll
    for (int r = 0; r < 4; r++)
        #pragma unroll
        for (int j = 0; j < 8; j++) c[r][j] = 0.f;

    #pragma unroll 1
    for (int kc = 0; kc < 4; kc++) {
        const float4* W4 = (const float4*)(W + kc * 32 * 128);
        float4* ws4 = (float4*)ws;
        #pragma unroll
        for (int i = tid; i < 1024; i += 256) ws4[i] = W4[i];
        #pragma unroll
        for (int i = tid; i < 512; i += 256) {
            int r = i >> 3, c4 = i & 7;
            int gr = row0 + r;
            float4 v = make_float4(0.f, 0.f, 0.f, 0.f);
            if (gr < n) v = ((const float4*)X)[gr * 32 + kc * 8 + c4];
            *(float4*)&xs[r * 36 + c4 * 4] = v;
        }
        __syncthreads();
        #pragma unroll 8
        for (int kk = 0; kk < 32; kk++) {
            float4 w0 = ((const float4*)ws)[kk * 32 + tx * 2];
            float4 w1 = ((const float4*)ws)[kk * 32 + tx * 2 + 1];
            #pragma unroll
            for (int r = 0; r < 4; r++) {
                float xv = xs[(ty * 4 + r) * 36 + kk];
                c[r][0] = fmaf(xv, w0.x, c[r][0]);
                c[r][1] = fmaf(xv, w0.y, c[r][1]);
                c[r][2] = fmaf(xv, w0.z, c[r][2]);
                c[r][3] = fmaf(xv, w0.w, c[r][3]);
                c[r][4] = fmaf(xv, w1.x, c[r][4]);
                c[r][5] = fmaf(xv, w1.y, c[r][5]);
                c[r][6] = fmaf(xv, w1.z, c[r][6]);
                c[r][7] = fmaf(xv, w1.w, c[r][7]);
            }
        }
        __syncthreads();
    }
    #pragma unroll
    for (int r = 0; r < 4; r++) {
        int gr = row0 + ty * 4 + r;
        if (gr < n) {
            g_h_tail[gr * 32 + tx * 2]     = make_float4(c[r][0], c[r][1], c[r][2], c[r][3]);
            g_h_tail[gr * 32 + tx * 2 + 1] = make_float4(c[r][4], c[r][5], c[r][6], c[r][7]);
        }
    }
}

// ---------------- h_l / h_r : row dot with precomputed w_l / w_r ----------------
// one warp per row; mode 0 -> (head_feature, g_wl, g_hl), 1 -> (tail_feature, g_wr, g_hr)
__global__ void hproj_kernel(const float* __restrict__ X, int n, int mode) {
    int warp = (blockIdx.x * blockDim.x + threadIdx.x) >> 5;
    int lane = threadIdx.x & 31;
    if (warp >= n) return;
    float4 x = ((const float4*)X)[warp * 32 + lane];
    const float* wv = mode ? g_wr : g_wl;
    float acc[4];
    #pragma unroll
    for (int h = 0; h < 4; h++) {
        float4 w = ((const float4*)wv)[h * 32 + lane];
        acc[h] = x.x * w.x + x.y * w.y + x.z * w.z + x.w * w.w;
    }
    #pragma unroll
    for (int off = 16; off; off >>= 1)
        #pragma unroll
        for (int h = 0; h < 4; h++)
            acc[h] += __shfl_xor_sync(0xFFFFFFFFu, acc[h], off);
    if (lane == 0) {
        float4 o = make_float4(acc[0], acc[1], acc[2], acc[3]);
        if (mode) g_hr[warp] = o; else g_hl[warp] = o;
    }
}

// ---------------- zero counts ----------------
__global__ void zero_kernel(int n) {
    int i = blockIdx.x * blockDim.x + threadIdx.x;
    if (i < n) g_count[i] = 0;
}

// ---------------- edge attention logits + head histogram ----------------
__global__ void att_kernel(const int* __restrict__ head, const int* __restrict__ tail,
                           const int* __restrict__ et, int E) {
    int e = blockIdx.x * blockDim.x + threadIdx.x;
    if (e >= E) return;
    int hi = head[e];
    float4 l = g_hl[hi];
    float4 r = g_hr[tail[e]];
    const float* he = &g_he[et[e] * 4];
    float4 a;
    a.x = l.x + r.x + he[0];
    a.y = l.y + r.y + he[1];
    a.z = l.z + r.z + he[2];
    a.w = l.w + r.w + he[3];
    a.x = (a.x >= 0.f) ? a.x : SLOPE * a.x;
    a.y = (a.y >= 0.f) ? a.y : SLOPE * a.y;
    a.z = (a.z >= 0.f) ? a.z : SLOPE * a.z;
    a.w = (a.w >= 0.f) ? a.w : SLOPE * a.w;
    g_att[e] = a;
    atomicAdd(&g_count[hi], 1);
}

// ---------------- exclusive scan of counts (single block) ----------------
__global__ void scan_kernel(int n, int E) {
    __shared__ int part[1024];
    int tid = threadIdx.x;
    int chunk = (n + 1023) / 1024;
    int beg = tid * chunk;
    int end = min(beg + chunk, n);
    int s = 0;
    for (int i = beg; i < end; i++) s += g_count[i];
    part[tid] = s;
    __syncthreads();
    for (int off = 1; off < 1024; off <<= 1) {
        int v = (tid >= off) ? part[tid - off] : 0;
        __syncthreads();
        part[tid] += v;
        __syncthreads();
    }
    int run = (tid > 0) ? part[tid - 1] : 0;
    for (int i = beg; i < end; i++) {
        int cc = g_count[i];
        g_off[i] = run;
        g_cursor[i] = run;
        run += cc;
    }
    if (tid == 1023) g_off[n] = E;
}

// ---------------- scatter edges into CSR order ----------------
__global__ void scatter_kernel(const int* __restrict__ head, const int* __restrict__ tail, int E) {
    int e = blockIdx.x * blockDim.x + threadIdx.x;
    if (e >= E) return;
    int hi = head[e];
    int p = atomicAdd(&g_cursor[hi], 1);
    g_satt[p] = g_att[e];
    g_stail[p] = tail[e];
}

// ---------------- per-node softmax + aggregation; one warp per head node ----------------
__global__ __launch_bounds__(256) void agg_kernel(float* __restrict__ out, int n) {
    __shared__ float4 sw[8][32];
    __shared__ int    st[8][32];
    int wi = threadIdx.x >> 5, lane = threadIdx.x & 31;
    int node = blockIdx.x * 8 + wi;
    if (node >= n) return;
    int beg = g_off[node], end = g_off[node + 1];
    if (beg == end) {
        ((float4*)out)[node * 32 + lane] = make_float4(0.f, 0.f, 0.f, 0.f);
        return;
    }
    int hsel = lane >> 3;       // which head this lane's 4 columns belong to
    // pass 1: per-head max
    float4 m = make_float4(-INFINITY, -INFINITY, -INFINITY, -INFINITY);
    for (int j = beg + lane; j < end; j += 32) {
        float4 a = g_satt[j];
        m.x = fmaxf(m.x, a.x); m.y = fmaxf(m.y, a.y);
        m.z = fmaxf(m.z, a.z); m.w = fmaxf(m.w, a.w);
    }
    #pragma unroll
    for (int off = 16; off; off >>= 1) {
        m.x = fmaxf(m.x, __shfl_xor_sync(0xFFFFFFFFu, m.x, off));
        m.y = fmaxf(m.y, __shfl_xor_sync(0xFFFFFFFFu, m.y, off));
        m.z = fmaxf(m.z, __shfl_xor_sync(0xFFFFFFFFu, m.z, off));
        m.w = fmaxf(m.w, __shfl_xor_sync(0xFFFFFFFFu, m.w, off));
    }
    // pass 2: exp weights + weighted accumulation of h_tail rows
    float4 acc = make_float4(0.f, 0.f, 0.f, 0.f);
    float4 den = make_float4(0.f, 0.f, 0.f, 0.f);
    for (int base = beg; base < end; base += 32) {
        int j = base + lane;
        float4 w = make_float4(0.f, 0.f, 0.f, 0.f);
        int t = 0;
        if (j < end) {
            float4 a = g_satt[j];
            w.x = __expf(a.x - m.x);
            w.y = __expf(a.y - m.y);
            w.z = __expf(a.z - m.z);
            w.w = __expf(a.w - m.w);
            t = g_stail[j];
        }
        den.x += w.x; den.y += w.y; den.z += w.z; den.w += w.w;
        sw[wi][lane] = w;
        st[wi][lane] = t;
        __syncwarp();
        int cnt = min(32, end - base);
        const float* swf = (const float*)&sw[wi][0];
        #pragma unroll 4
        for (int q = 0; q < cnt; q++) {
            float wq = swf[q * 4 + hsel];
            float4 hv = g_h_tail[st[wi][q] * 32 + lane];
            acc.x = fmaf(wq, hv.x, acc.x);
            acc.y = fmaf(wq, hv.y, acc.y);
            acc.z = fmaf(wq, hv.z, acc.z);
            acc.w = fmaf(wq, hv.w, acc.w);
        }
        __syncwarp();
    }
    #pragma unroll
    for (int off = 16; off; off >>= 1) {
        den.x += __shfl_xor_sync(0xFFFFFFFFu, den.x, off);
        den.y += __shfl_xor_sync(0xFFFFFFFFu, den.y, off);
        den.z += __shfl_xor_sync(0xFFFFFFFFu, den.z, off);
        den.w += __shfl_xor_sync(0xFFFFFFFFu, den.w, off);
    }
    float d = (hsel == 0) ? den.x : (hsel == 1) ? den.y : (hsel == 2) ? den.z : den.w;
    float inv = 1.f / d;
    float4 o;
    o.x = acc.x * inv; o.y = acc.y * inv; o.z = acc.z * inv; o.w = acc.w * inv;
    o.x = (o.x > 0.f) ? o.x : expm1f(o.x);
    o.y = (o.y > 0.f) ? o.y : expm1f(o.y);
    o.z = (o.z > 0.f) ? o.z : expm1f(o.z);
    o.w = (o.w > 0.f) ? o.w : expm1f(o.w);
    ((float4*)out)[node * 32 + lane] = o;
}

// ---------------- launch ----------------
extern "C" void kernel_launch(void* const* d_in, const int* in_sizes, int n_in,
                              void* d_out, int out_size) {
    const float* head_feature = (const float*)d_in[0];
    const float* tail_feature = (const float*)d_in[1];
    const int*   edge_list    = (const int*)d_in[2];
    const int*   tmp_edge     = (const int*)d_in[3];
    const float* W            = (const float*)d_in[4];
    const float* We           = (const float*)d_in[5];
    const float* al           = (const float*)d_in[6];
    const float* ar           = (const float*)d_in[7];
    const float* ae           = (const float*)d_in[8];
    const float* emb          = (const float*)d_in[9];
    float* out = (float*)d_out;

    int n = in_sizes[0] / IN_F;          // 100000
    int E = in_sizes[3];                 // 1600000
    const int* head = edge_list;
    const int* tail = edge_list + E;

    prep_kernel<<<1, 512>>>(W, We, al, ar, ae, emb);
    zero_kernel<<<(n + 255) / 256, 256>>>(n);
    gemm128_kernel<<<(n + 63) / 64, 256>>>(tail_feature, W, n);
    hproj_kernel<<<(n * 32 + 255) / 256, 256>>>(head_feature, n, 0);
    hproj_kernel<<<(n * 32 + 255) / 256, 256>>>(tail_feature, n, 1);
    att_kernel<<<(E + 255) / 256, 256>>>(head, tail, tmp_edge, E);
    scan_kernel<<<1, 1024>>>(n, E);
    scatter_kernel<<<(E + 255) / 256, 256>>>(head, tail, E);
    agg_kernel<<<(n + 7) / 8, 256>>>(out, n);
}

// round 5
// speedup vs baseline: 2.3379x; 2.3379x over previous
#include <cuda_runtime.h>
#include <math.h>

#define N_NODES 100000
#define N_EDGES 1600000
#define IN_F 128
#define NHEAD 4
#define SLOPE 0.2f

typedef unsigned long long u64;

// ---------------- scratch (device globals; no allocation) ----------------
__device__ float4 g_h_tail[N_NODES * 32];   // [N,128] as float4  (51.2MB)
__device__ float4 g_hl[N_NODES];            // [N,4]
__device__ float4 g_hr[N_NODES];            // [N,4]
__device__ float4 g_satt[N_EDGES];          // CSR-ordered att
__device__ int    g_stail[N_EDGES];         // CSR-ordered tail index
__device__ int    g_count[N_NODES];
__device__ int    g_off[N_NODES + 1];
__device__ int    g_cursor[N_NODES];
__device__ int    g_bsum[256];
__device__ int    g_bbase[256];
__device__ float  g_wl[NHEAD * IN_F];       // W @ a_l per head
__device__ float  g_he[8 * NHEAD];          // per (etype, head) scalar

// ---------------- f32x2 helpers ----------------
__device__ __forceinline__ u64 fma2(u64 a, u64 b, u64 c) {
    u64 d;
    asm("fma.rn.f32x2 %0, %1, %2, %3;" : "=l"(d) : "l"(a), "l"(b), "l"(c));
    return d;
}
__device__ __forceinline__ u64 pack2(float x) {
    u64 d;
    unsigned r = __float_as_uint(x);
    asm("mov.b64 %0, {%1, %1};" : "=l"(d) : "r"(r));
    return d;
}
__device__ __forceinline__ float2 unpack2(u64 v) {
    float2 f;
    asm("mov.b64 {%0, %1}, %2;" : "=f"(f.x), "=f"(f.y) : "l"(v));
    return f;
}

// ---------------- tiny prep: w_l, edge-type table ----------------
__global__ void prep_kernel(const float* __restrict__ W,
                            const float* __restrict__ We,
                            const float* __restrict__ al,
                            const float* __restrict__ ae,
                            const float* __restrict__ emb) {
    int tid = threadIdx.x;
    if (tid < 512) {
        int h = tid >> 7, i = tid & 127;
        float sl = 0.f;
        #pragma unroll 8
        for (int d = 0; d < 32; d++)
            sl = fmaf(W[i * 128 + h * 32 + d], al[h * 32 + d], sl);
        g_wl[h * 128 + i] = sl;
    }
    __shared__ float u[32 * 4];
    if (tid < 128) {
        int k = tid >> 2, h = tid & 3;
        float s = 0.f;
        for (int de = 0; de < 32; de++)
            s = fmaf(We[k * 128 + h * 32 + de], ae[h * 32 + de], s);
        u[k * 4 + h] = s;
    }
    __syncthreads();
    if (tid < 32) {
        int t = tid >> 2, h = tid & 3;
        float s = 0.f;
        for (int k = 0; k < 32; k++)
            s = fmaf(emb[t * 32 + k], u[k * 4 + h], s);
        g_he[t * 4 + h] = s;
    }
}

// ---------------- GEMM (f32x2) + fused hr epilogue ----------------
// block: 256 threads, 64 rows x 128 cols; columns paired into f32x2.
__global__ __launch_bounds__(256) void gemm128_kernel(const float* __restrict__ X,
                                                      const float* __restrict__ W,
                                                      const float* __restrict__ ar,
                                                      int n) {
    __shared__ float ws[32 * 128];
    __shared__ float xs[64 * 36];
    int tid = threadIdx.x;
    int tx = tid & 15, ty = tid >> 4;
    int row0 = blockIdx.x * 64;
    u64 c2[4][4];
    #pragma unroll
    for (int r = 0; r < 4; r++)
        #pragma unroll
        for (int j = 0; j < 4; j++) c2[r][j] = 0ull;

    #pragma unroll 1
    for (int kc = 0; kc < 4; kc++) {
        const float4* W4 = (const float4*)(W + kc * 32 * 128);
        float4* ws4 = (float4*)ws;
        #pragma unroll
        for (int i = tid; i < 1024; i += 256) ws4[i] = W4[i];
        #pragma unroll
        for (int i = tid; i < 512; i += 256) {
            int r = i >> 3, c4 = i & 7;
            int gr = row0 + r;
            float4 v = make_float4(0.f, 0.f, 0.f, 0.f);
            if (gr < n) v = ((const float4*)X)[gr * 32 + kc * 8 + c4];
            *(float4*)&xs[r * 36 + c4 * 4] = v;
        }
        __syncthreads();
        #pragma unroll 8
        for (int kk = 0; kk < 32; kk++) {
            // 128 floats per k-row = 32 ulonglong2; thread tx owns cols [tx*8, tx*8+8)
            ulonglong2 wa = ((const ulonglong2*)ws)[kk * 32 + tx * 2];
            ulonglong2 wb = ((const ulonglong2*)ws)[kk * 32 + tx * 2 + 1];
            #pragma unroll
            for (int r = 0; r < 4; r++) {
                u64 xp = pack2(xs[(ty * 4 + r) * 36 + kk]);
                c2[r][0] = fma2(xp, wa.x, c2[r][0]);
                c2[r][1] = fma2(xp, wa.y, c2[r][1]);
                c2[r][2] = fma2(xp, wb.x, c2[r][2]);
                c2[r][3] = fma2(xp, wb.y, c2[r][3]);
            }
        }
        __syncthreads();
    }

    // epilogue: store h_tail + fused hr = sum_d a_r[h,d]*h_tail[row,h*32+d]
    int h = tx >> 2;
    int o = (tx & 3) * 8;
    float arr[8];
    #pragma unroll
    for (int j = 0; j < 8; j++) arr[j] = ar[h * 32 + o + j];
    #pragma unroll
    for (int r = 0; r < 4; r++) {
        int gr = row0 + ty * 4 + r;
        float2 f0 = unpack2(c2[r][0]);
        float2 f1 = unpack2(c2[r][1]);
        float2 f2 = unpack2(c2[r][2]);
        float2 f3 = unpack2(c2[r][3]);
        if (gr < n) {
            g_h_tail[gr * 32 + tx * 2]     = make_float4(f0.x, f0.y, f1.x, f1.y);
            g_h_tail[gr * 32 + tx * 2 + 1] = make_float4(f2.x, f2.y, f3.x, f3.y);
        }
        float p = f0.x * arr[0] + f0.y * arr[1] + f1.x * arr[2] + f1.y * arr[3]
                + f2.x * arr[4] + f2.y * arr[5] + f3.x * arr[6] + f3.y * arr[7];
        p += __shfl_xor_sync(0xFFFFFFFFu, p, 1);
        p += __shfl_xor_sync(0xFFFFFFFFu, p, 2);
        if ((tx & 3) == 0 && gr < n)
            ((float*)&g_hr[gr])[h] = p;
    }
}

// ---------------- hl : 4 rows per warp, dot with precomputed w_l ----------------
__global__ void hl_kernel(const float* __restrict__ X, int n) {
    int warp = (blockIdx.x * blockDim.x + threadIdx.x) >> 5;
    int lane = threadIdx.x & 31;
    int row0 = warp * 4;
    if (row0 >= n) return;
    float4 x[4];
    #pragma unroll
    for (int r = 0; r < 4; r++) {
        int gr = row0 + r;
        x[r] = (gr < n) ? ((const float4*)X)[gr * 32 + lane]
                        : make_float4(0.f, 0.f, 0.f, 0.f);
    }
    float4 wv[4];
    #pragma unroll
    for (int h = 0; h < 4; h++) wv[h] = ((const float4*)g_wl)[h * 32 + lane];
    float acc[4][4];
    #pragma unroll
    for (int r = 0; r < 4; r++)
        #pragma unroll
        for (int h = 0; h < 4; h++)
            acc[r][h] = x[r].x * wv[h].x + x[r].y * wv[h].y
                      + x[r].z * wv[h].z + x[r].w * wv[h].w;
    #pragma unroll
    for (int off = 16; off; off >>= 1)
        #pragma unroll
        for (int r = 0; r < 4; r++)
            #pragma unroll
            for (int h = 0; h < 4; h++)
                acc[r][h] += __shfl_xor_sync(0xFFFFFFFFu, acc[r][h], off);
    if (lane < 4 && row0 + lane < n) {
        int r = lane;
        g_hl[row0 + r] = make_float4(acc[r][0], acc[r][1], acc[r][2], acc[r][3]);
    }
}

// ---------------- zero counts ----------------
__global__ void zero_kernel(int n) {
    int i = blockIdx.x * blockDim.x + threadIdx.x;
    if (i < n) g_count[i] = 0;
}

// ---------------- head histogram ----------------
__global__ void hist_kernel(const int* __restrict__ head, int E) {
    int e = blockIdx.x * blockDim.x + threadIdx.x;
    if (e < E) atomicAdd(&g_count[head[e]], 1);
}

// ---------------- 3-phase exclusive scan of counts ----------------
__global__ void scan1_kernel(int n) {
    __shared__ int sh[512];
    int tid = threadIdx.x;
    int i = blockIdx.x * 512 + tid;
    int v = (i < n) ? g_count[i] : 0;
    sh[tid] = v;
    __syncthreads();
    #pragma unroll
    for (int off = 256; off; off >>= 1) {
        if (tid < off) sh[tid] += sh[tid + off];
        __syncthreads();
    }
    if (tid == 0) g_bsum[blockIdx.x] = sh[0];
}

__global__ void scan2_kernel(int nb, int n, int E) {
    __shared__ int sh[256];
    int tid = threadIdx.x;
    int v = (tid < nb) ? g_bsum[tid] : 0;
    sh[tid] = v;
    __syncthreads();
    #pragma unroll
    for (int off = 1; off < 256; off <<= 1) {
        int t = (tid >= off) ? sh[tid - off] : 0;
        __syncthreads();
        sh[tid] += t;
        __syncthreads();
    }
    g_bbase[tid] = sh[tid] - v;       // exclusive
    if (tid == 0) g_off[n] = E;
}

__global__ void scan3_kernel(int n) {
    __shared__ int sh[512];
    int tid = threadIdx.x;
    int i = blockIdx.x * 512 + tid;
    int v = (i < n) ? g_count[i] : 0;
    sh[tid] = v;
    __syncthreads();
    #pragma unroll
    for (int off = 1; off < 512; off <<= 1) {
        int t = (tid >= off) ? sh[tid - off] : 0;
        __syncthreads();
        sh[tid] += t;
        __syncthreads();
    }
    if (i < n) {
        int off = g_bbase[blockIdx.x] + sh[tid] - v;   // exclusive
        g_off[i] = off;
        g_cursor[i] = off;
    }
}

// ---------------- fused attention + CSR scatter ----------------
__global__ void scatter_att_kernel(const int* __restrict__ head,
                                   const int* __restrict__ tail,
                                   const int* __restrict__ et, int E) {
    int e = blockIdx.x * blockDim.x + threadIdx.x;
    if (e >= E) return;
    int hi = head[e];
    int ti = tail[e];
    float4 l = g_hl[hi];
    float4 r = g_hr[ti];
    const float* he = &g_he[et[e] * 4];
    float4 a;
    a.x = l.x + r.x + he[0];
    a.y = l.y + r.y + he[1];
    a.z = l.z + r.z + he[2];
    a.w = l.w + r.w + he[3];
    a.x = (a.x >= 0.f) ? a.x : SLOPE * a.x;
    a.y = (a.y >= 0.f) ? a.y : SLOPE * a.y;
    a.z = (a.z >= 0.f) ? a.z : SLOPE * a.z;
    a.w = (a.w >= 0.f) ? a.w : SLOPE * a.w;
    int p = atomicAdd(&g_cursor[hi], 1);
    g_satt[p] = a;
    g_stail[p] = ti;
}

// ---------------- per-node softmax + aggregation; one warp per head node ----------------
__global__ __launch_bounds__(256) void agg_kernel(float* __restrict__ out, int n) {
    __shared__ float4 sw[8][32];
    __shared__ int    st[8][32];
    int wi = threadIdx.x >> 5, lane = threadIdx.x & 31;
    int node = blockIdx.x * 8 + wi;
    if (node >= n) return;
    int beg = g_off[node], end = g_off[node + 1];
    if (beg == end) {
        ((float4*)out)[node * 32 + lane] = make_float4(0.f, 0.f, 0.f, 0.f);
        return;
    }
    int hsel = lane >> 3;
    // pass 1: per-head max
    float4 m = make_float4(-INFINITY, -INFINITY, -INFINITY, -INFINITY);
    for (int j = beg + lane; j < end; j += 32) {
        float4 a = g_satt[j];
        m.x = fmaxf(m.x, a.x); m.y = fmaxf(m.y, a.y);
        m.z = fmaxf(m.z, a.z); m.w = fmaxf(m.w, a.w);
    }
    #pragma unroll
    for (int off = 16; off; off >>= 1) {
        m.x = fmaxf(m.x, __shfl_xor_sync(0xFFFFFFFFu, m.x, off));
        m.y = fmaxf(m.y, __shfl_xor_sync(0xFFFFFFFFu, m.y, off));
        m.z = fmaxf(m.z, __shfl_xor_sync(0xFFFFFFFFu, m.z, off));
        m.w = fmaxf(m.w, __shfl_xor_sync(0xFFFFFFFFu, m.w, off));
    }
    // pass 2: exp weights + weighted accumulation of h_tail rows
    float4 acc = make_float4(0.f, 0.f, 0.f, 0.f);
    float4 den = make_float4(0.f, 0.f, 0.f, 0.f);
    for (int base = beg; base < end; base += 32) {
        int j = base + lane;
        float4 w = make_float4(0.f, 0.f, 0.f, 0.f);
        int t = 0;
        if (j < end) {
            float4 a = g_satt[j];
            w.x = __expf(a.x - m.x);
            w.y = __expf(a.y - m.y);
            w.z = __expf(a.z - m.z);
            w.w = __expf(a.w - m.w);
            t = g_stail[j];
        }
        den.x += w.x; den.y += w.y; den.z += w.z; den.w += w.w;
        sw[wi][lane] = w;
        st[wi][lane] = t;
        __syncwarp();
        int cnt = min(32, end - base);
        const float* swf = (const float*)&sw[wi][0];
        #pragma unroll 4
        for (int q = 0; q < cnt; q++) {
            float wq = swf[q * 4 + hsel];
            float4 hv = g_h_tail[st[wi][q] * 32 + lane];
            acc.x = fmaf(wq, hv.x, acc.x);
            acc.y = fmaf(wq, hv.y, acc.y);
            acc.z = fmaf(wq, hv.z, acc.z);
            acc.w = fmaf(wq, hv.w, acc.w);
        }
        __syncwarp();
    }
    #pragma unroll
    for (int off = 16; off; off >>= 1) {
        den.x += __shfl_xor_sync(0xFFFFFFFFu, den.x, off);
        den.y += __shfl_xor_sync(0xFFFFFFFFu, den.y, off);
        den.z += __shfl_xor_sync(0xFFFFFFFFu, den.z, off);
        den.w += __shfl_xor_sync(0xFFFFFFFFu, den.w, off);
    }
    float d = (hsel == 0) ? den.x : (hsel == 1) ? den.y : (hsel == 2) ? den.z : den.w;
    float inv = 1.f / d;
    float4 o;
    o.x = acc.x * inv; o.y = acc.y * inv; o.z = acc.z * inv; o.w = acc.w * inv;
    o.x = (o.x > 0.f) ? o.x : expm1f(o.x);
    o.y = (o.y > 0.f) ? o.y : expm1f(o.y);
    o.z = (o.z > 0.f) ? o.z : expm1f(o.z);
    o.w = (o.w > 0.f) ? o.w : expm1f(o.w);
    ((float4*)out)[node * 32 + lane] = o;
}

// ---------------- launch ----------------
extern "C" void kernel_launch(void* const* d_in, const int* in_sizes, int n_in,
                              void* d_out, int out_size) {
    const float* head_feature = (const float*)d_in[0];
    const float* tail_feature = (const float*)d_in[1];
    const int*   edge_list    = (const int*)d_in[2];
    const int*   tmp_edge     = (const int*)d_in[3];
    const float* W            = (const float*)d_in[4];
    const float* We           = (const float*)d_in[5];
    const float* al           = (const float*)d_in[6];
    const float* ar           = (const float*)d_in[7];
    const float* ae           = (const float*)d_in[8];
    const float* emb          = (const float*)d_in[9];
    float* out = (float*)d_out;

    int nh = in_sizes[0] / IN_F;         // head nodes
    int nt = in_sizes[1] / IN_F;         // tail nodes
    int E  = in_sizes[3];
    const int* head = edge_list;
    const int* tail = edge_list + E;
    int nb = (nh + 511) / 512;           // scan blocks (<=256)

    prep_kernel<<<1, 512>>>(W, We, al, ae, emb);
    zero_kernel<<<(nh + 255) / 256, 256>>>(nh);
    hist_kernel<<<(E + 255) / 256, 256>>>(head, E);
    gemm128_kernel<<<(nt + 63) / 64, 256>>>(tail_feature, W, ar, nt);
    hl_kernel<<<(nh * 8 + 255) / 256, 256>>>(head_feature, nh);
    scan1_kernel<<<nb, 512>>>(nh);
    scan2_kernel<<<1, 256>>>(nb, nh, E);
    scan3_kernel<<<nb, 512>>>(nh);
    scatter_att_kernel<<<(E + 255) / 256, 256>>>(head, tail, tmp_edge, E);
    agg_kernel<<<(nh + 7) / 8, 256>>>(out, nh);
}

// round 7
// speedup vs baseline: 2.4908x; 1.0654x over previous
#include <cuda_runtime.h>
#include <cuda_fp16.h>
#include <math.h>

#define N_NODES 100000
#define N_EDGES 1600000
#define IN_F 128
#define NHEAD 4
#define SLOPE 0.2f

typedef unsigned long long u64;

// ---------------- scratch (device globals; no allocation) ----------------
__device__ uint2  g_ht16[N_NODES * 32];     // h_tail fp16 [N,128] as 4-half uint2 (25.6MB)
__device__ float4 g_hl[N_NODES];            // [N,4]
__device__ float4 g_hr[N_NODES];            // [N,4]
__device__ float4 g_satt[N_EDGES];          // CSR-ordered att
__device__ int    g_stail[N_EDGES];         // CSR-ordered tail index
__device__ int    g_count[N_NODES];
__device__ int    g_off[N_NODES + 1];
__device__ int    g_cursor[N_NODES];
__device__ int    g_bsum[256];
__device__ int    g_bbase[256];
__device__ float  g_wl[NHEAD * IN_F];       // W @ a_l per head
__device__ float  g_he[8 * NHEAD];          // per (etype, head) scalar

// ---------------- f32x2 helpers ----------------
__device__ __forceinline__ u64 fma2(u64 a, u64 b, u64 c) {
    u64 d;
    asm("fma.rn.f32x2 %0, %1, %2, %3;" : "=l"(d) : "l"(a), "l"(b), "l"(c));
    return d;
}
__device__ __forceinline__ u64 pack2(float x) {
    u64 d;
    unsigned r = __float_as_uint(x);
    asm("mov.b64 %0, {%1, %1};" : "=l"(d) : "r"(r));
    return d;
}
__device__ __forceinline__ float2 unpack2(u64 v) {
    float2 f;
    asm("mov.b64 {%0, %1}, %2;" : "=f"(f.x), "=f"(f.y) : "l"(v));
    return f;
}
__device__ __forceinline__ unsigned h2_as_u32(__half2 h) {
    unsigned u;
    asm("mov.b32 %0, %1;" : "=r"(u) : "r"(*(unsigned*)&h));
    return u;
}

// ---------------- tiny prep: w_l, edge-type table ----------------
__global__ void prep_kernel(const float* __restrict__ W,
                            const float* __restrict__ We,
                            const float* __restrict__ al,
                            const float* __restrict__ ae,
                            const float* __restrict__ emb) {
    int tid = threadIdx.x;
    if (tid < 512) {
        int h = tid >> 7, i = tid & 127;
        float sl = 0.f;
        #pragma unroll 8
        for (int d = 0; d < 32; d++)
            sl = fmaf(W[i * 128 + h * 32 + d], al[h * 32 + d], sl);
        g_wl[h * 128 + i] = sl;
    }
    __shared__ float u[32 * 4];
    if (tid < 128) {
        int k = tid >> 2, h = tid & 3;
        float s = 0.f;
        for (int de = 0; de < 32; de++)
            s = fmaf(We[k * 128 + h * 32 + de], ae[h * 32 + de], s);
        u[k * 4 + h] = s;
    }
    __syncthreads();
    if (tid < 32) {
        int t = tid >> 2, h = tid & 3;
        float s = 0.f;
        for (int k = 0; k < 32; k++)
            s = fmaf(emb[t * 32 + k], u[k * 4 + h], s);
        g_he[t * 4 + h] = s;
    }
}

// ---------------- GEMM: 128x128 tile, thread = 16 rows x 4 cols (f32x2 row pairs) ----------------
// warp w: rows [w*16, w*16+16); lane l: cols [l*4, l*4+4).
__global__ __launch_bounds__(256) void gemm128_kernel(const float* __restrict__ X,
                                                      const float* __restrict__ W,
                                                      const float* __restrict__ ar,
                                                      int n) {
    __shared__ float ws[32 * 128];    // [kk][col] 16KB
    __shared__ float xs[32 * 128];    // [kk][row] 16KB (transposed)
    int tid = threadIdx.x;
    int lane = tid & 31, wid = tid >> 5;
    int row0 = blockIdx.x * 128;
    u64 c2[8][4];
    #pragma unroll
    for (int rp = 0; rp < 8; rp++)
        #pragma unroll
        for (int j = 0; j < 4; j++) c2[rp][j] = 0ull;

    #pragma unroll 1
    for (int kc = 0; kc < 4; kc++) {
        // W chunk: rows kc*32..+32 of W (contiguous) -> ws[kk][col]
        const float4* W4 = (const float4*)W + kc * 1024;
        float4* ws4 = (float4*)ws;
        #pragma unroll
        for (int i = tid; i < 1024; i += 256) ws4[i] = W4[i];
        // X chunk transposed: xs[kk][row]
        #pragma unroll
        for (int j = 0; j < 4; j++) {
            int i = tid + j * 256;
            int r = i & 127, c4 = i >> 7;          // c4 in 0..7
            float4 v = make_float4(0.f, 0.f, 0.f, 0.f);
            if (row0 + r < n) v = ((const float4*)X)[(row0 + r) * 32 + kc * 8 + c4];
            xs[(c4 * 4 + 0) * 128 + r] = v.x;
            xs[(c4 * 4 + 1) * 128 + r] = v.y;
            xs[(c4 * 4 + 2) * 128 + r] = v.z;
            xs[(c4 * 4 + 3) * 128 + r] = v.w;
        }
        __syncthreads();
        #pragma unroll 4
        for (int kk = 0; kk < 32; kk++) {
            float4 wv = *(const float4*)&ws[kk * 128 + lane * 4];
            u64 wp0 = pack2(wv.x), wp1 = pack2(wv.y);
            u64 wp2 = pack2(wv.z), wp3 = pack2(wv.w);
            const u64* xrow = (const u64*)&xs[kk * 128 + wid * 16];
            #pragma unroll
            for (int rp = 0; rp < 8; rp++) {
                u64 xp = xrow[rp];                 // rows (2rp, 2rp+1), broadcast
                c2[rp][0] = fma2(xp, wp0, c2[rp][0]);
                c2[rp][1] = fma2(xp, wp1, c2[rp][1]);
                c2[rp][2] = fma2(xp, wp2, c2[rp][2]);
                c2[rp][3] = fma2(xp, wp3, c2[rp][3]);
            }
        }
        __syncthreads();
    }

    // epilogue: fp16 h_tail store + fused hr = sum_d a_r[h,d]*h_tail[row,h*32+d]
    int h = lane >> 3;
    float arr[4];
    #pragma unroll
    for (int q = 0; q < 4; q++) arr[q] = ar[h * 32 + (lane & 7) * 4 + q];
    #pragma unroll
    for (int rp = 0; rp < 8; rp++) {
        float2 f0 = unpack2(c2[rp][0]);
        float2 f1 = unpack2(c2[rp][1]);
        float2 f2 = unpack2(c2[rp][2]);
        float2 f3 = unpack2(c2[rp][3]);
        int re = row0 + wid * 16 + rp * 2;
        int ro = re + 1;
        // even row: values (f0.x, f1.x, f2.x, f3.x); odd row: .y
        if (re < n) {
            __half2 a01 = __floats2half2_rn(f0.x, f1.x);
            __half2 a23 = __floats2half2_rn(f2.x, f3.x);
            g_ht16[re * 32 + lane] = make_uint2(h2_as_u32(a01), h2_as_u32(a23));
        }
        if (ro < n) {
            __half2 b01 = __floats2half2_rn(f0.y, f1.y);
            __half2 b23 = __floats2half2_rn(f2.y, f3.y);
            g_ht16[ro * 32 + lane] = make_uint2(h2_as_u32(b01), h2_as_u32(b23));
        }
        float pe = f0.x * arr[0] + f1.x * arr[1] + f2.x * arr[2] + f3.x * arr[3];
        float po = f0.y * arr[0] + f1.y * arr[1] + f2.y * arr[2] + f3.y * arr[3];
        #pragma unroll
        for (int off = 1; off < 8; off <<= 1) {
            pe += __shfl_xor_sync(0xFFFFFFFFu, pe, off);
            po += __shfl_xor_sync(0xFFFFFFFFu, po, off);
        }
        if ((lane & 7) == 0) {
            if (re < n) ((float*)&g_hr[re])[h] = pe;
            if (ro < n) ((float*)&g_hr[ro])[h] = po;
        }
    }
}

// ---------------- hl : 4 rows per warp, dot with precomputed w_l ----------------
__global__ void hl_kernel(const float* __restrict__ X, int n) {
    int warp = (blockIdx.x * blockDim.x + threadIdx.x) >> 5;
    int lane = threadIdx.x & 31;
    int row0 = warp * 4;
    if (row0 >= n) return;
    float4 x[4];
    #pragma unroll
    for (int r = 0; r < 4; r++) {
        int gr = row0 + r;
        x[r] = (gr < n) ? ((const float4*)X)[gr * 32 + lane]
                        : make_float4(0.f, 0.f, 0.f, 0.f);
    }
    float4 wv[4];
    #pragma unroll
    for (int h = 0; h < 4; h++) wv[h] = ((const float4*)g_wl)[h * 32 + lane];
    float acc[4][4];
    #pragma unroll
    for (int r = 0; r < 4; r++)
        #pragma unroll
        for (int h = 0; h < 4; h++)
            acc[r][h] = x[r].x * wv[h].x + x[r].y * wv[h].y
                      + x[r].z * wv[h].z + x[r].w * wv[h].w;
    #pragma unroll
    for (int off = 16; off; off >>= 1)
        #pragma unroll
        for (int r = 0; r < 4; r++)
            #pragma unroll
            for (int h = 0; h < 4; h++)
                acc[r][h] += __shfl_xor_sync(0xFFFFFFFFu, acc[r][h], off);
    if (lane < 4 && row0 + lane < n) {
        int r = lane;
        g_hl[row0 + r] = make_float4(acc[r][0], acc[r][1], acc[r][2], acc[r][3]);
    }
}

// ---------------- zero counts ----------------
__global__ void zero_kernel(int n) {
    int i = blockIdx.x * blockDim.x + threadIdx.x;
    if (i < n) g_count[i] = 0;
}

// ---------------- head histogram ----------------
__global__ void hist_kernel(const int* __restrict__ head, int E) {
    int e = blockIdx.x * blockDim.x + threadIdx.x;
    if (e < E) atomicAdd(&g_count[head[e]], 1);
}

// ---------------- 3-phase exclusive scan of counts ----------------
__global__ void scan1_kernel(int n) {
    __shared__ int sh[512];
    int tid = threadIdx.x;
    int i = blockIdx.x * 512 + tid;
    int v = (i < n) ? g_count[i] : 0;
    sh[tid] = v;
    __syncthreads();
    #pragma unroll
    for (int off = 256; off; off >>= 1) {
        if (tid < off) sh[tid] += sh[tid + off];
        __syncthreads();
    }
    if (tid == 0) g_bsum[blockIdx.x] = sh[0];
}

__global__ void scan2_kernel(int nb, int n, int E) {
    __shared__ int sh[256];
    int tid = threadIdx.x;
    int v = (tid < nb) ? g_bsum[tid] : 0;
    sh[tid] = v;
    __syncthreads();
    #pragma unroll
    for (int off = 1; off < 256; off <<= 1) {
        int t = (tid >= off) ? sh[tid - off] : 0;
        __syncthreads();
        sh[tid] += t;
        __syncthreads();
    }
    g_bbase[tid] = sh[tid] - v;       // exclusive
    if (tid == 0) g_off[n] = E;
}

__global__ void scan3_kernel(int n) {
    __shared__ int sh[512];
    int tid = threadIdx.x;
    int i = blockIdx.x * 512 + tid;
    int v = (i < n) ? g_count[i] : 0;
    sh[tid] = v;
    __syncthreads();
    #pragma unroll
    for (int off = 1; off < 512; off <<= 1) {
        int t = (tid >= off) ? sh[tid - off] : 0;
        __syncthreads();
        sh[tid] += t;
        __syncthreads();
    }
    if (i < n) {
        int off = g_bbase[blockIdx.x] + sh[tid] - v;   // exclusive
        g_off[i] = off;
        g_cursor[i] = off;
    }
}

// ---------------- fused attention + CSR scatter ----------------
__global__ void scatter_att_kernel(const int* __restrict__ head,
                                   const int* __restrict__ tail,
                                   const int* __restrict__ et, int E) {
    int e = blockIdx.x * blockDim.x + threadIdx.x;
    if (e >= E) return;
    int hi = head[e];
    int ti = tail[e];
    float4 l = g_hl[hi];
    float4 r = g_hr[ti];
    const float* he = &g_he[et[e] * 4];
    float4 a;
    a.x = l.x + r.x + he[0];
    a.y = l.y + r.y + he[1];
    a.z = l.z + r.z + he[2];
    a.w = l.w + r.w + he[3];
    a.x = (a.x >= 0.f) ? a.x : SLOPE * a.x;
    a.y = (a.y >= 0.f) ? a.y : SLOPE * a.y;
    a.z = (a.z >= 0.f) ? a.z : SLOPE * a.z;
    a.w = (a.w >= 0.f) ? a.w : SLOPE * a.w;
    int p = atomicAdd(&g_cursor[hi], 1);
    g_satt[p] = a;
    g_stail[p] = ti;
}

// ---------------- per-node softmax + aggregation; one warp per head node ----------------
__global__ __launch_bounds__(256) void agg_kernel(float* __restrict__ out, int n) {
    __shared__ float4 sw[8][32];
    __shared__ int    st[8][32];
    int wi = threadIdx.x >> 5, lane = threadIdx.x & 31;
    int node = blockIdx.x * 8 + wi;
    if (node >= n) return;
    int beg = g_off[node], end = g_off[node + 1];
    if (beg == end) {
        ((float4*)out)[node * 32 + lane] = make_float4(0.f, 0.f, 0.f, 0.f);
        return;
    }
    int hsel = lane >> 3;
    // pass 1: per-head max
    float4 m = make_float4(-INFINITY, -INFINITY, -INFINITY, -INFINITY);
    for (int j = beg + lane; j < end; j += 32) {
        float4 a = g_satt[j];
        m.x = fmaxf(m.x, a.x); m.y = fmaxf(m.y, a.y);
        m.z = fmaxf(m.z, a.z); m.w = fmaxf(m.w, a.w);
    }
    #pragma unroll
    for (int off = 16; off; off >>= 1) {
        m.x = fmaxf(m.x, __shfl_xor_sync(0xFFFFFFFFu, m.x, off));
        m.y = fmaxf(m.y, __shfl_xor_sync(0xFFFFFFFFu, m.y, off));
        m.z = fmaxf(m.z, __shfl_xor_sync(0xFFFFFFFFu, m.z, off));
        m.w = fmaxf(m.w, __shfl_xor_sync(0xFFFFFFFFu, m.w, off));
    }
    // pass 2: exp weights + weighted accumulation of fp16 h_tail rows (fp32 accum)
    float4 acc = make_float4(0.f, 0.f, 0.f, 0.f);
    float4 den = make_float4(0.f, 0.f, 0.f, 0.f);
    for (int base = beg; base < end; base += 32) {
        int j = base + lane;
        float4 w = make_float4(0.f, 0.f, 0.f, 0.f);
        int t = 0;
        if (j < end) {
            float4 a = g_satt[j];
            w.x = __expf(a.x - m.x);
            w.y = __expf(a.y - m.y);
            w.z = __expf(a.z - m.z);
            w.w = __expf(a.w - m.w);
            t = g_stail[j];
        }
        den.x += w.x; den.y += w.y; den.z += w.z; den.w += w.w;
        sw[wi][lane] = w;
        st[wi][lane] = t;
        __syncwarp();
        int cnt = min(32, end - base);
        const float* swf = (const float*)&sw[wi][0];
        #pragma unroll 4
        for (int q = 0; q < cnt; q++) {
            float wq = swf[q * 4 + hsel];
            uint2 p = g_ht16[st[wi][q] * 32 + lane];
            float2 f01 = __half22float2(*(__half2*)&p.x);
            float2 f23 = __half22float2(*(__half2*)&p.y);
            acc.x = fmaf(wq, f01.x, acc.x);
            acc.y = fmaf(wq, f01.y, acc.y);
            acc.z = fmaf(wq, f23.x, acc.z);
            acc.w = fmaf(wq, f23.y, acc.w);
        }
        __syncwarp();
    }
    #pragma unroll
    for (int off = 16; off; off >>= 1) {
        den.x += __shfl_xor_sync(0xFFFFFFFFu, den.x, off);
        den.y += __shfl_xor_sync(0xFFFFFFFFu, den.y, off);
        den.z += __shfl_xor_sync(0xFFFFFFFFu, den.z, off);
        den.w += __shfl_xor_sync(0xFFFFFFFFu, den.w, off);
    }
    float d = (hsel == 0) ? den.x : (hsel == 1) ? den.y : (hsel == 2) ? den.z : den.w;
    float inv = 1.f / d;
    float4 o;
    o.x = acc.x * inv; o.y = acc.y * inv; o.z = acc.z * inv; o.w = acc.w * inv;
    o.x = (o.x > 0.f) ? o.x : expm1f(o.x);
    o.y = (o.y > 0.f) ? o.y : expm1f(o.y);
    o.z = (o.z > 0.f) ? o.z : expm1f(o.z);
    o.w = (o.w > 0.f) ? o.w : expm1f(o.w);
    ((float4*)out)[node * 32 + lane] = o;
}

// ---------------- launch ----------------
extern "C" void kernel_launch(void* const* d_in, const int* in_sizes, int n_in,
                              void* d_out, int out_size) {
    const float* head_feature = (const float*)d_in[0];
    const float* tail_feature = (const float*)d_in[1];
    const int*   edge_list    = (const int*)d_in[2];
    const int*   tmp_edge     = (const int*)d_in[3];
    const float* W            = (const float*)d_in[4];
    const float* We           = (const float*)d_in[5];
    const float* al           = (const float*)d_in[6];
    const float* ar           = (const float*)d_in[7];
    const float* ae           = (const float*)d_in[8];
    const float* emb          = (const float*)d_in[9];
    float* out = (float*)d_out;

    int nh = in_sizes[0] / IN_F;         // head nodes
    int nt = in_sizes[1] / IN_F;         // tail nodes
    int E  = in_sizes[3];
    const int* head = edge_list;
    const int* tail = edge_list + E;
    int nb = (nh + 511) / 512;           // scan blocks (<=256)

    prep_kernel<<<1, 512>>>(W, We, al, ae, emb);
    zero_kernel<<<(nh + 255) / 256, 256>>>(nh);
    hist_kernel<<<(E + 255) / 256, 256>>>(head, E);
    gemm128_kernel<<<(nt + 127) / 128, 256>>>(tail_feature, W, ar, nt);
    hl_kernel<<<(nh * 8 + 255) / 256, 256>>>(head_feature, nh);
    scan1_kernel<<<nb, 512>>>(nh);
    scan2_kernel<<<1, 256>>>(nb, nh, E);
    scan3_kernel<<<nb, 512>>>(nh);
    scatter_att_kernel<<<(E + 255) / 256, 256>>>(head, tail, tmp_edge, E);
    agg_kernel<<<(nh + 7) / 8, 256>>>(out, nh);
}

// round 9
// speedup vs baseline: 3.0769x; 1.2353x over previous
#include <cuda_runtime.h>
#include <cuda_fp16.h>
#include <math.h>

#define N_NODES 100000
#define N_EDGES 1600000
#define IN_F 128
#define NHEAD 4
#define SLOPE 0.2f

typedef unsigned long long u64;

// ---------------- scratch (device globals; no allocation) ----------------
__device__ uint2  g_ht16[N_NODES * 32];     // h_tail fp16 [N,128] as 4-half uint2 (25.6MB)
__device__ float4 g_hl[N_NODES];            // [N,4]
__device__ float4 g_hr[N_NODES];            // [N,4]
__device__ float4 g_satt[N_EDGES];          // CSR-ordered att
__device__ int    g_stail[N_EDGES];         // CSR-ordered tail index
__device__ int    g_count[N_NODES];
__device__ int    g_off[N_NODES + 1];
__device__ int    g_cursor[N_NODES];
__device__ int    g_bsum[256];
__device__ int    g_bbase[256];
__device__ float  g_wl[NHEAD * IN_F];       // W @ a_l per head
__device__ float  g_he[8 * NHEAD];          // per (etype, head) scalar

// ---------------- f32x2 helpers ----------------
__device__ __forceinline__ u64 fma2(u64 a, u64 b, u64 c) {
    u64 d;
    asm("fma.rn.f32x2 %0, %1, %2, %3;" : "=l"(d) : "l"(a), "l"(b), "l"(c));
    return d;
}
__device__ __forceinline__ u64 pack2(float x) {
    u64 d;
    unsigned r = __float_as_uint(x);
    asm("mov.b64 %0, {%1, %1};" : "=l"(d) : "r"(r));
    return d;
}
__device__ __forceinline__ float2 unpack2(u64 v) {
    float2 f;
    asm("mov.b64 {%0, %1}, %2;" : "=f"(f.x), "=f"(f.y) : "l"(v));
    return f;
}
__device__ __forceinline__ unsigned h2_as_u32(__half2 h) {
    unsigned u;
    asm("mov.b32 %0, %1;" : "=r"(u) : "r"(*(unsigned*)&h));
    return u;
}

// ---------------- tiny prep: w_l, edge-type table ----------------
__global__ void prep_kernel(const float* __restrict__ W,
                            const float* __restrict__ We,
                            const float* __restrict__ al,
                            const float* __restrict__ ae,
                            const float* __restrict__ emb) {
    int tid = threadIdx.x;
    if (tid < 512) {
        int h = tid >> 7, i = tid & 127;
        float sl = 0.f;
        #pragma unroll 8
        for (int d = 0; d < 32; d++)
            sl = fmaf(W[i * 128 + h * 32 + d], al[h * 32 + d], sl);
        g_wl[h * 128 + i] = sl;
    }
    __shared__ float u[32 * 4];
    if (tid < 128) {
        int k = tid >> 2, h = tid & 3;
        float s = 0.f;
        for (int de = 0; de < 32; de++)
            s = fmaf(We[k * 128 + h * 32 + de], ae[h * 32 + de], s);
        u[k * 4 + h] = s;
    }
    __syncthreads();
    if (tid < 32) {
        int t = tid >> 2, h = tid & 3;
        float s = 0.f;
        for (int k = 0; k < 32; k++)
            s = fmaf(emb[t * 32 + k], u[k * 4 + h], s);
        g_he[t * 4 + h] = s;
    }
}

// ---------------- GEMM: 128x128 tile, thread = 16 rows x 4 cols (f32x2 row pairs) ----------------
// warp w: rows [w*16, w*16+16); lane l: cols [l*4, l*4+4). Software-pipelined inner loop.
// NOTE: one xs row = 128 floats = 32 ulonglong2 -> row stride 32 in xs_x units.
__global__ __launch_bounds__(256, 2) void gemm128_kernel(const float* __restrict__ X,
                                                         const float* __restrict__ W,
                                                         const float* __restrict__ ar,
                                                         int n) {
    __shared__ float ws[32 * 128];    // [kk][col] 16KB
    __shared__ float xs[32 * 128];    // [kk][row] 16KB (transposed)
    int tid = threadIdx.x;
    int lane = tid & 31, wid = tid >> 5;
    int row0 = blockIdx.x * 128;
    u64 c2[8][4];
    #pragma unroll
    for (int rp = 0; rp < 8; rp++)
        #pragma unroll
        for (int j = 0; j < 4; j++) c2[rp][j] = 0ull;

    const float* ws_w = &ws[lane * 4];
    const ulonglong2* xs_x = (const ulonglong2*)&xs[wid * 16];   // +kk*32 per k-row

    #pragma unroll 1
    for (int kc = 0; kc < 4; kc++) {
        // W chunk: rows kc*32..+32 of W (contiguous) -> ws[kk][col]
        const float4* W4 = (const float4*)W + kc * 1024;
        float4* ws4 = (float4*)ws;
        #pragma unroll
        for (int i = tid; i < 1024; i += 256) ws4[i] = W4[i];
        // X chunk transposed: xs[kk][row]
        #pragma unroll
        for (int j = 0; j < 4; j++) {
            int i = tid + j * 256;
            int r = i & 127, c4 = i >> 7;          // c4 in 0..7
            float4 v = make_float4(0.f, 0.f, 0.f, 0.f);
            if (row0 + r < n) v = ((const float4*)X)[(row0 + r) * 32 + kc * 8 + c4];
            xs[(c4 * 4 + 0) * 128 + r] = v.x;
            xs[(c4 * 4 + 1) * 128 + r] = v.y;
            xs[(c4 * 4 + 2) * 128 + r] = v.z;
            xs[(c4 * 4 + 3) * 128 + r] = v.w;
        }
        __syncthreads();

        // prologue: load kk=0
        float4 wv = *(const float4*)&ws_w[0];
        ulonglong2 x01 = xs_x[0];
        ulonglong2 x23 = xs_x[1];
        ulonglong2 x45 = xs_x[2];
        ulonglong2 x67 = xs_x[3];

        #pragma unroll 8
        for (int kk = 0; kk < 32; kk++) {
            // prefetch kk+1 before the FMA run (clamped: last iter re-reads kk=31, values unused)
            int kn = (kk < 31) ? (kk + 1) : 31;
            float4 wv_n = *(const float4*)&ws_w[kn * 128];
            ulonglong2 x01n = xs_x[kn * 32 + 0];
            ulonglong2 x23n = xs_x[kn * 32 + 1];
            ulonglong2 x45n = xs_x[kn * 32 + 2];
            ulonglong2 x67n = xs_x[kn * 32 + 3];
            u64 wp0 = pack2(wv.x), wp1 = pack2(wv.y);
            u64 wp2 = pack2(wv.z), wp3 = pack2(wv.w);
            c2[0][0] = fma2(x01.x, wp0, c2[0][0]);
            c2[0][1] = fma2(x01.x, wp1, c2[0][1]);
            c2[0][2] = fma2(x01.x, wp2, c2[0][2]);
            c2[0][3] = fma2(x01.x, wp3, c2[0][3]);
            c2[1][0] = fma2(x01.y, wp0, c2[1][0]);
            c2[1][1] = fma2(x01.y, wp1, c2[1][1]);
            c2[1][2] = fma2(x01.y, wp2, c2[1][2]);
            c2[1][3] = fma2(x01.y, wp3, c2[1][3]);
            c2[2][0] = fma2(x23.x, wp0, c2[2][0]);
            c2[2][1] = fma2(x23.x, wp1, c2[2][1]);
            c2[2][2] = fma2(x23.x, wp2, c2[2][2]);
            c2[2][3] = fma2(x23.x, wp3, c2[2][3]);
            c2[3][0] = fma2(x23.y, wp0, c2[3][0]);
            c2[3][1] = fma2(x23.y, wp1, c2[3][1]);
            c2[3][2] = fma2(x23.y, wp2, c2[3][2]);
            c2[3][3] = fma2(x23.y, wp3, c2[3][3]);
            c2[4][0] = fma2(x45.x, wp0, c2[4][0]);
            c2[4][1] = fma2(x45.x, wp1, c2[4][1]);
            c2[4][2] = fma2(x45.x, wp2, c2[4][2]);
            c2[4][3] = fma2(x45.x, wp3, c2[4][3]);
            c2[5][0] = fma2(x45.y, wp0, c2[5][0]);
            c2[5][1] = fma2(x45.y, wp1, c2[5][1]);
            c2[5][2] = fma2(x45.y, wp2, c2[5][2]);
            c2[5][3] = fma2(x45.y, wp3, c2[5][3]);
            c2[6][0] = fma2(x67.x, wp0, c2[6][0]);
            c2[6][1] = fma2(x67.x, wp1, c2[6][1]);
            c2[6][2] = fma2(x67.x, wp2, c2[6][2]);
            c2[6][3] = fma2(x67.x, wp3, c2[6][3]);
            c2[7][0] = fma2(x67.y, wp0, c2[7][0]);
            c2[7][1] = fma2(x67.y, wp1, c2[7][1]);
            c2[7][2] = fma2(x67.y, wp2, c2[7][2]);
            c2[7][3] = fma2(x67.y, wp3, c2[7][3]);
            wv = wv_n;
            x01 = x01n; x23 = x23n; x45 = x45n; x67 = x67n;
        }
        __syncthreads();
    }

    // epilogue: fp16 h_tail store + fused hr = sum_d a_r[h,d]*h_tail[row,h*32+d]
    int h = lane >> 3;
    float arr[4];
    #pragma unroll
    for (int q = 0; q < 4; q++) arr[q] = ar[h * 32 + (lane & 7) * 4 + q];
    #pragma unroll
    for (int rp = 0; rp < 8; rp++) {
        float2 f0 = unpack2(c2[rp][0]);
        float2 f1 = unpack2(c2[rp][1]);
        float2 f2 = unpack2(c2[rp][2]);
        float2 f3 = unpack2(c2[rp][3]);
        int re = row0 + wid * 16 + rp * 2;
        int ro = re + 1;
        // even row: values (f0.x, f1.x, f2.x, f3.x); odd row: .y
        if (re < n) {
            __half2 a01 = __floats2half2_rn(f0.x, f1.x);
            __half2 a23 = __floats2half2_rn(f2.x, f3.x);
            g_ht16[re * 32 + lane] = make_uint2(h2_as_u32(a01), h2_as_u32(a23));
        }
        if (ro < n) {
            __half2 b01 = __floats2half2_rn(f0.y, f1.y);
            __half2 b23 = __floats2half2_rn(f2.y, f3.y);
            g_ht16[ro * 32 + lane] = make_uint2(h2_as_u32(b01), h2_as_u32(b23));
        }
        float pe = f0.x * arr[0] + f1.x * arr[1] + f2.x * arr[2] + f3.x * arr[3];
        float po = f0.y * arr[0] + f1.y * arr[1] + f2.y * arr[2] + f3.y * arr[3];
        #pragma unroll
        for (int off = 1; off < 8; off <<= 1) {
            pe += __shfl_xor_sync(0xFFFFFFFFu, pe, off);
            po += __shfl_xor_sync(0xFFFFFFFFu, po, off);
        }
        if ((lane & 7) == 0) {
            if (re < n) ((float*)&g_hr[re])[h] = pe;
            if (ro < n) ((float*)&g_hr[ro])[h] = po;
        }
    }
}

// ---------------- hl : 4 rows per warp, dot with precomputed w_l ----------------
__global__ void hl_kernel(const float* __restrict__ X, int n) {
    int warp = (blockIdx.x * blockDim.x + threadIdx.x) >> 5;
    int lane = threadIdx.x & 31;
    int row0 = warp * 4;
    if (row0 >= n) return;
    float4 x[4];
    #pragma unroll
    for (int r = 0; r < 4; r++) {
        int gr = row0 + r;
        x[r] = (gr < n) ? ((const float4*)X)[gr * 32 + lane]
                        : make_float4(0.f, 0.f, 0.f, 0.f);
    }
    float4 wv[4];
    #pragma unroll
    for (int h = 0; h < 4; h++) wv[h] = ((const float4*)g_wl)[h * 32 + lane];
    float acc[4][4];
    #pragma unroll
    for (int r = 0; r < 4; r++)
        #pragma unroll
        for (int h = 0; h < 4; h++)
            acc[r][h] = x[r].x * wv[h].x + x[r].y * wv[h].y
                      + x[r].z * wv[h].z + x[r].w * wv[h].w;
    #pragma unroll
    for (int off = 16; off; off >>= 1)
        #pragma unroll
        for (int r = 0; r < 4; r++)
            #pragma unroll
            for (int h = 0; h < 4; h++)
                acc[r][h] += __shfl_xor_sync(0xFFFFFFFFu, acc[r][h], off);
    if (lane < 4 && row0 + lane < n) {
        int r = lane;
        g_hl[row0 + r] = make_float4(acc[r][0], acc[r][1], acc[r][2], acc[r][3]);
    }
}

// ---------------- zero counts ----------------
__global__ void zero_kernel(int n) {
    int i = blockIdx.x * blockDim.x + threadIdx.x;
    if (i < n) g_count[i] = 0;
}

// ---------------- head histogram ----------------
__global__ void hist_kernel(const int* __restrict__ head, int E) {
    int e = blockIdx.x * blockDim.x + threadIdx.x;
    if (e < E) atomicAdd(&g_count[head[e]], 1);
}

// ---------------- 3-phase exclusive scan of counts ----------------
__global__ void scan1_kernel(int n) {
    __shared__ int sh[512];
    int tid = threadIdx.x;
    int i = blockIdx.x * 512 + tid;
    int v = (i < n) ? g_count[i] : 0;
    sh[tid] = v;
    __syncthreads();
    #pragma unroll
    for (int off = 256; off; off >>= 1) {
        if (tid < off) sh[tid] += sh[tid + off];
        __syncthreads();
    }
    if (tid == 0) g_bsum[blockIdx.x] = sh[0];
}

__global__ void scan2_kernel(int nb, int n, int E) {
    __shared__ int sh[256];
    int tid = threadIdx.x;
    int v = (tid < nb) ? g_bsum[tid] : 0;
    sh[tid] = v;
    __syncthreads();
    #pragma unroll
    for (int off = 1; off < 256; off <<= 1) {
        int t = (tid >= off) ? sh[tid - off] : 0;
        __syncthreads();
        sh[tid] += t;
        __syncthreads();
    }
    g_bbase[tid] = sh[tid] - v;       // exclusive
    if (tid == 0) g_off[n] = E;
}

__global__ void scan3_kernel(int n) {
    __shared__ int sh[512];
    int tid = threadIdx.x;
    int i = blockIdx.x * 512 + tid;
    int v = (i < n) ? g_count[i] : 0;
    sh[tid] = v;
    __syncthreads();
    #pragma unroll
    for (int off = 1; off < 512; off <<= 1) {
        int t = (tid >= off) ? sh[tid - off] : 0;
        __syncthreads();
        sh[tid] += t;
        __syncthreads();
    }
    if (i < n) {
        int off = g_bbase[blockIdx.x] + sh[tid] - v;   // exclusive
        g_off[i] = off;
        g_cursor[i] = off;
    }
}

// ---------------- fused attention + CSR scatter ----------------
__global__ void scatter_att_kernel(const int* __restrict__ head,
                                   const int* __restrict__ tail,
                                   const int* __restrict__ et, int E) {
    int e = blockIdx.x * blockDim.x + threadIdx.x;
    if (e >= E) return;
    int hi = head[e];
    int ti = tail[e];
    float4 l = g_hl[hi];
    float4 r = g_hr[ti];
    const float* he = &g_he[et[e] * 4];
    float4 a;
    a.x = l.x + r.x + he[0];
    a.y = l.y + r.y + he[1];
    a.z = l.z + r.z + he[2];
    a.w = l.w + r.w + he[3];
    a.x = (a.x >= 0.f) ? a.x : SLOPE * a.x;
    a.y = (a.y >= 0.f) ? a.y : SLOPE * a.y;
    a.z = (a.z >= 0.f) ? a.z : SLOPE * a.z;
    a.w = (a.w >= 0.f) ? a.w : SLOPE * a.w;
    int p = atomicAdd(&g_cursor[hi], 1);
    g_satt[p] = a;
    g_stail[p] = ti;
}

// ---------------- per-node softmax + aggregation; one warp per head node ----------------
// single pass: softmax shift-invariance => no segment-max needed (|logit| << 88)
__global__ __launch_bounds__(256) void agg_kernel(float* __restrict__ out, int n) {
    __shared__ float4 sw[8][32];
    __shared__ int    st[8][32];
    int wi = threadIdx.x >> 5, lane = threadIdx.x & 31;
    int node = blockIdx.x * 8 + wi;
    if (node >= n) return;
    int beg = g_off[node], end = g_off[node + 1];
    if (beg == end) {
        ((float4*)out)[node * 32 + lane] = make_float4(0.f, 0.f, 0.f, 0.f);
        return;
    }
    int hsel = lane >> 3;
    float4 acc = make_float4(0.f, 0.f, 0.f, 0.f);
    float4 den = make_float4(0.f, 0.f, 0.f, 0.f);
    for (int base = beg; base < end; base += 32) {
        int j = base + lane;
        float4 w = make_float4(0.f, 0.f, 0.f, 0.f);
        int t = 0;
        if (j < end) {
            float4 a = g_satt[j];
            w.x = __expf(a.x);
            w.y = __expf(a.y);
            w.z = __expf(a.z);
            w.w = __expf(a.w);
            t = g_stail[j];
        }
        den.x += w.x; den.y += w.y; den.z += w.z; den.w += w.w;
        sw[wi][lane] = w;
        st[wi][lane] = t;
        __syncwarp();
        int cnt = min(32, end - base);
        const float* swf = (const float*)&sw[wi][0];
        #pragma unroll 4
        for (int q = 0; q < cnt; q++) {
            float wq = swf[q * 4 + hsel];
            uint2 p = g_ht16[st[wi][q] * 32 + lane];
            float2 f01 = __half22float2(*(__half2*)&p.x);
            float2 f23 = __half22float2(*(__half2*)&p.y);
            acc.x = fmaf(wq, f01.x, acc.x);
            acc.y = fmaf(wq, f01.y, acc.y);
            acc.z = fmaf(wq, f23.x, acc.z);
            acc.w = fmaf(wq, f23.y, acc.w);
        }
        __syncwarp();
    }
    #pragma unroll
    for (int off = 16; off; off >>= 1) {
        den.x += __shfl_xor_sync(0xFFFFFFFFu, den.x, off);
        den.y += __shfl_xor_sync(0xFFFFFFFFu, den.y, off);
        den.z += __shfl_xor_sync(0xFFFFFFFFu, den.z, off);
        den.w += __shfl_xor_sync(0xFFFFFFFFu, den.w, off);
    }
    float d = (hsel == 0) ? den.x : (hsel == 1) ? den.y : (hsel == 2) ? den.z : den.w;
    float inv = 1.f / d;
    float4 o;
    o.x = acc.x * inv; o.y = acc.y * inv; o.z = acc.z * inv; o.w = acc.w * inv;
    o.x = (o.x > 0.f) ? o.x : expm1f(o.x);
    o.y = (o.y > 0.f) ? o.y : expm1f(o.y);
    o.z = (o.z > 0.f) ? o.z : expm1f(o.z);
    o.w = (o.w > 0.f) ? o.w : expm1f(o.w);
    ((float4*)out)[node * 32 + lane] = o;
}

// ---------------- launch ----------------
extern "C" void kernel_launch(void* const* d_in, const int* in_sizes, int n_in,
                              void* d_out, int out_size) {
    const float* head_feature = (const float*)d_in[0];
    const float* tail_feature = (const float*)d_in[1];
    const int*   edge_list    = (const int*)d_in[2];
    const int*   tmp_edge     = (const int*)d_in[3];
    const float* W            = (const float*)d_in[4];
    const float* We           = (const float*)d_in[5];
    const float* al           = (const float*)d_in[6];
    const float* ar           = (const float*)d_in[7];
    const float* ae           = (const float*)d_in[8];
    const float* emb          = (const float*)d_in[9];
    float* out = (float*)d_out;

    int nh = in_sizes[0] / IN_F;         // head nodes
    int nt = in_sizes[1] / IN_F;         // tail nodes
    int E  = in_sizes[3];
    const int* head = edge_list;
    const int* tail = edge_list + E;
    int nb = (nh + 511) / 512;           // scan blocks (<=256)

    prep_kernel<<<1, 512>>>(W, We, al, ae, emb);
    zero_kernel<<<(nh + 255) / 256, 256>>>(nh);
    hist_kernel<<<(E + 255) / 256, 256>>>(head, E);
    gemm128_kernel<<<(nt + 127) / 128, 256>>>(tail_feature, W, ar, nt);
    hl_kernel<<<(nh * 8 + 255) / 256, 256>>>(head_feature, nh);
    scan1_kernel<<<nb, 512>>>(nh);
    scan2_kernel<<<1, 256>>>(nb, nh, E);
    scan3_kernel<<<nb, 512>>>(nh);
    scatter_att_kernel<<<(E + 255) / 256, 256>>>(head, tail, tmp_edge, E);
    agg_kernel<<<(nh + 7) / 8, 256>>>(out, nh);
}